// round 9
// baseline (speedup 1.0000x reference)
#include <cuda_runtime.h>
#include <cuda.h>
#include <cstdint>

// Problem constants
#define BATCH 32
#define NQ    512
#define HD    1024
#define OD    1024
#define NSUBJ 8

// Tiling: CTA 64x128, 4 warps each computing 32x64; K chunk = 32 floats (128B SW128 rows)
#define BM 64
#define BN 128
#define BKF 32
#define CHUNKS (HD / BKF)    // 32
#define NST 4                // pipeline stages
#define THREADS 128

// SMEM layout
#define SMB_FULL(s)  ((s) * 8)          // NST full barriers
#define SMB_EMPTY(s) (32 + (s) * 8)     // NST empty barriers
#define SM_A(s)      (1024 + (s) * 24576)            // 64 rows * 128B
#define SM_B(s)      (SM_A(s) + 8192)                // 128 rows * 128B
#define STAGE_BYTES  24576
#define SMEM_TOTAL   (1024 + NST * STAGE_BYTES)      // 99328

__device__ __forceinline__ uint32_t smem_u32(const void* p) {
    return (uint32_t)__cvta_generic_to_shared(p);
}
__device__ __forceinline__ void mbar_init(uint32_t a, uint32_t cnt) {
    asm volatile("mbarrier.init.shared.b64 [%0], %1;" :: "r"(a), "r"(cnt) : "memory");
}
__device__ __forceinline__ void mbar_expect_tx(uint32_t a, uint32_t bytes) {
    asm volatile("mbarrier.arrive.expect_tx.shared.b64 _, [%0], %1;"
                 :: "r"(a), "r"(bytes) : "memory");
}
__device__ __forceinline__ void mbar_arrive(uint32_t a) {
    asm volatile("mbarrier.arrive.shared.b64 _, [%0];" :: "r"(a) : "memory");
}
__device__ __forceinline__ void mbar_wait(uint32_t a, uint32_t parity) {
    asm volatile(
        "{\n\t.reg .pred P;\n"
        "WL%=:\n\tmbarrier.try_wait.parity.shared.b64 P, [%0], %1;\n"
        "\t@P bra WD%=;\n\tbra WL%=;\nWD%=:\n\t}"
        :: "r"(a), "r"(parity) : "memory");
}
__device__ __forceinline__ void tma_load_3d(uint32_t dst, const CUtensorMap* tm,
                                            int cx, int cy, int cz, uint32_t mbar) {
    asm volatile(
        "cp.async.bulk.tensor.3d.shared::cta.global.tile.mbarrier::complete_tx::bytes "
        "[%0], [%1, {%2, %3, %4}], [%5];"
        :: "r"(dst), "l"(tm), "r"(cx), "r"(cy), "r"(cz), "r"(mbar) : "memory");
}
__device__ __forceinline__ uint32_t f2tf32(float f) {
    uint32_t r;
    asm("cvt.rna.tf32.f32 %0, %1;\n" : "=r"(r) : "f"(f));
    return r;
}

// ---------------- main GEMM ----------------
__global__ __launch_bounds__(THREADS, 2)
void scl_tf32_v7(const __grid_constant__ CUtensorMap tma_x,
                 const __grid_constant__ CUtensorMap tma_w,
                 const int*   __restrict__ sid,
                 const float* __restrict__ bias,
                 float*       __restrict__ y) {
    extern __shared__ char smem[];
    const uint32_t sb = smem_u32(smem);

    const int b  = blockIdx.z;
    const int s  = __ldg(&sid[b]);
    const int m0 = blockIdx.y * BM;     // N (query) tile
    const int n0 = blockIdx.x * BN;     // O tile

    const int tid  = threadIdx.x;
    const int wid  = tid >> 5;
    const int lane = tid & 31;
    const int g    = lane >> 2;         // groupID 0..7
    const int tg   = lane & 3;          // threadInGroup 0..3
    const int gx   = g << 2;            // SW128 XOR term (word units)
    const int wm   = (wid & 1) * 32;    // warp M offset (0/32)
    const int wn   = (wid >> 1) * 64;   // warp N offset (0/64)

    // Barrier init + initial TMA issues
    if (tid == 0) {
        for (int st = 0; st < NST; st++) {
            mbar_init(sb + SMB_FULL(st), 1);
            mbar_init(sb + SMB_EMPTY(st), 4);
        }
    }
    __syncthreads();
    if (tid == 0) {
        for (int c = 0; c < NST; c++) {
            mbar_expect_tx(sb + SMB_FULL(c), STAGE_BYTES);
            tma_load_3d(sb + SM_A(c), &tma_x, c * BKF, m0, b, sb + SMB_FULL(c));
            tma_load_3d(sb + SM_B(c), &tma_w, c * BKF, n0, s, sb + SMB_FULL(c));
        }
    }

    float acc[2][8][4];
    #pragma unroll
    for (int i = 0; i < 2; i++)
        #pragma unroll
        for (int j = 0; j < 8; j++)
            #pragma unroll
            for (int k = 0; k < 4; k++) acc[i][j][k] = 0.f;

    uint32_t af0[2][4], bf0[8][2];   // frag buffer 0
    uint32_t af1[2][4], bf1[8][2];   // frag buffer 1

    // Fragment load from SW128-swizzled tiles (A: 64x32f, B: 128x32f).
    // A (x): raw fp32 — HW truncates to tf32.
    // B (W): RNA-rounded here (numerically == pre-rounding prologue).
    auto ldfrag = [&](uint32_t af[2][4], uint32_t bf[8][2],
                      const float* A, const float* Bsm, int kl) {
        const int c0k = (kl + tg) ^ gx;
        const int c1k = (kl + tg + 4) ^ gx;
        #pragma unroll
        for (int mi = 0; mi < 2; mi++) {
            const int r0 = wm + mi * 16 + g;
            af[mi][0] = __float_as_uint(A[ r0      * 32 + c0k]);
            af[mi][1] = __float_as_uint(A[(r0 + 8) * 32 + c0k]);
            af[mi][2] = __float_as_uint(A[ r0      * 32 + c1k]);
            af[mi][3] = __float_as_uint(A[(r0 + 8) * 32 + c1k]);
        }
        #pragma unroll
        for (int ni = 0; ni < 8; ni++) {
            const int c0 = wn + ni * 8 + g;
            bf[ni][0] = f2tf32(Bsm[c0 * 32 + c0k]);
            bf[ni][1] = f2tf32(Bsm[c0 * 32 + c1k]);
        }
    };

    auto domma = [&](uint32_t af[2][4], uint32_t bf[8][2]) {
        #pragma unroll
        for (int mi = 0; mi < 2; mi++)
            #pragma unroll
            for (int ni = 0; ni < 8; ni++) {
                asm volatile(
                    "mma.sync.aligned.m16n8k8.row.col.f32.tf32.tf32.f32 "
                    "{%0,%1,%2,%3}, {%4,%5,%6,%7}, {%8,%9}, {%0,%1,%2,%3};\n"
                    : "+f"(acc[mi][ni][0]), "+f"(acc[mi][ni][1]),
                      "+f"(acc[mi][ni][2]), "+f"(acc[mi][ni][3])
                    : "r"(af[mi][0]), "r"(af[mi][1]),
                      "r"(af[mi][2]), "r"(af[mi][3]),
                      "r"(bf[ni][0]), "r"(bf[ni][1]));
            }
    };

    // Wait chunk 0, preload its ks=0 fragments
    mbar_wait(sb + SMB_FULL(0), 0);
    ldfrag(af0, bf0, (const float*)(smem + SM_A(0)), (const float*)(smem + SM_B(0)), 0);

    int wp = 0;   // parity of the NEXT full-wait
    for (int kt = 0; kt < CHUNKS; kt++) {
        const int st = kt % NST;
        const float* A   = (const float*)(smem + SM_A(st));
        const float* Bsm = (const float*)(smem + SM_B(st));

        ldfrag(af1, bf1, A, Bsm, 8);
        domma(af0, bf0);
        ldfrag(af0, bf0, A, Bsm, 16);
        domma(af1, bf1);
        ldfrag(af1, bf1, A, Bsm, 24);
        domma(af0, bf0);

        if (kt + 1 < CHUNKS) {
            const int ns = (kt + 1) % NST;
            if (ns == 0) wp ^= 1;
            mbar_wait(sb + SMB_FULL(ns), (uint32_t)wp);
            ldfrag(af0, bf0, (const float*)(smem + SM_A(ns)),
                             (const float*)(smem + SM_B(ns)), 0);
        }
        domma(af1, bf1);

        // Signal this stage consumed
        if (lane == 0) mbar_arrive(sb + SMB_EMPTY(st));

        // Producer: refill this slot with chunk kt+NST once all 4 warps arrived
        if (tid == 0 && kt + NST < CHUNKS) {
            mbar_wait(sb + SMB_EMPTY(st), (uint32_t)((kt / NST) & 1));
            mbar_expect_tx(sb + SMB_FULL(st), STAGE_BYTES);
            const int c = kt + NST;
            tma_load_3d(sb + SM_A(st), &tma_x, c * BKF, m0, b, sb + SMB_FULL(st));
            tma_load_3d(sb + SM_B(st), &tma_w, c * BKF, n0, s, sb + SMB_FULL(st));
        }
    }

    // Epilogue: bias add + store
    const float* bb = bias + (size_t)s * OD + n0;
    float* yb = y + (size_t)b * NQ * OD + (size_t)m0 * OD + n0;

    #pragma unroll
    for (int mi = 0; mi < 2; mi++) {
        const int row = wm + mi * 16 + g;
        #pragma unroll
        for (int ni = 0; ni < 8; ni++) {
            const int col = wn + ni * 8 + tg * 2;
            const float b0v = __ldg(&bb[col]);
            const float b1v = __ldg(&bb[col + 1]);
            float2 v0 = make_float2(acc[mi][ni][0] + b0v, acc[mi][ni][1] + b1v);
            float2 v1 = make_float2(acc[mi][ni][2] + b0v, acc[mi][ni][3] + b1v);
            *reinterpret_cast<float2*>(&yb[(size_t)row * OD + col])       = v0;
            *reinterpret_cast<float2*>(&yb[(size_t)(row + 8) * OD + col]) = v1;
        }
    }
}

// ---------------- host launch ----------------
typedef int (*PFN_encodeTiled)(
    CUtensorMap*, int, unsigned int, void*,
    const unsigned long long*, const unsigned long long*,
    const unsigned int*, const unsigned int*,
    int, int, int, int);

extern "C" void kernel_launch(void* const* d_in, const int* in_sizes, int n_in,
                              void* d_out, int out_size) {
    const float* x    = (const float*)d_in[0];
    const int*   sid  = (const int*)  d_in[1];
    const float* w    = (const float*)d_in[2];
    const float* bias = (const float*)d_in[3];
    float* y = (float*)d_out;

    PFN_encodeTiled enc = nullptr;
    cudaDriverEntryPointQueryResult qr;
    cudaGetDriverEntryPoint("cuTensorMapEncodeTiled", (void**)&enc, cudaEnableDefault, &qr);

    // Enum ABI values: FLOAT32=7, interleave NONE=0, SWIZZLE_128B=3, L2_128B=2, OOB NONE=0
    CUtensorMap tx{}, tw{};
    {
        unsigned long long dims[3]    = {HD, NQ, BATCH};
        unsigned long long strides[2] = {HD * 4ull, (unsigned long long)NQ * HD * 4ull};
        unsigned int box[3]           = {BKF, BM, 1};
        unsigned int es[3]            = {1, 1, 1};
        enc(&tx, 7, 3, (void*)x, dims, strides, box, es, 0, 3, 2, 0);
    }
    {
        unsigned long long dims[3]    = {HD, OD, NSUBJ};
        unsigned long long strides[2] = {HD * 4ull, (unsigned long long)OD * HD * 4ull};
        unsigned int box[3]           = {BKF, BN, 1};
        unsigned int es[3]            = {1, 1, 1};
        enc(&tw, 7, 3, (void*)w, dims, strides, box, es, 0, 3, 2, 0);
    }

    cudaFuncSetAttribute(scl_tf32_v7, cudaFuncAttributeMaxDynamicSharedMemorySize, SMEM_TOTAL);

    dim3 grid(OD / BN, NQ / BM, BATCH);  // (8, 8, 32) = 2048 CTAs
    scl_tf32_v7<<<grid, THREADS, SMEM_TOTAL>>>(tx, tw, sid, bias, y);
}

// round 10
// speedup vs baseline: 1.1515x; 1.1515x over previous
#include <cuda_runtime.h>
#include <cuda.h>
#include <cstdint>

// Problem constants
#define BATCH 32
#define NQ    512
#define HD    1024
#define OD    1024
#define NSUBJ 8

// Tiling: CTA 128x128, 4 warps each computing 64x64; K chunk = 32 floats
#define BM 128
#define BN 128
#define BKF 32
#define CHUNKS (HD / BKF)    // 32
#define NST 3
#define THREADS 128

// SMEM layout
#define SMB_FULL(s)  ((s) * 8)
#define SMB_EMPTY(s) (24 + (s) * 8)
#define SM_A(s)      (1024 + (s) * 32768)
#define SM_B(s)      (SM_A(s) + 16384)
#define STAGE_BYTES  32768
#define SMEM_TOTAL   (1024 + NST * STAGE_BYTES)   // 99328

// Repacked W scratch: [s*32+c][o][32 floats], RNA-rounded to tf32, column-paired
// with per-row XOR baked in: slot q (0..15) holds logical cols (base, base+4),
// stored j = 2q+half;  q = ( (k&24)>>1 | (k&3) ) ^ ((o&3)<<2),  half = (k>>2)&1.
__device__ float g_wp[(size_t)NSUBJ * CHUNKS * OD * BKF];

__device__ __forceinline__ uint32_t smem_u32(const void* p) {
    return (uint32_t)__cvta_generic_to_shared(p);
}
__device__ __forceinline__ void mbar_init(uint32_t a, uint32_t cnt) {
    asm volatile("mbarrier.init.shared.b64 [%0], %1;" :: "r"(a), "r"(cnt) : "memory");
}
__device__ __forceinline__ void mbar_expect_tx(uint32_t a, uint32_t bytes) {
    asm volatile("mbarrier.arrive.expect_tx.shared.b64 _, [%0], %1;"
                 :: "r"(a), "r"(bytes) : "memory");
}
__device__ __forceinline__ void mbar_arrive(uint32_t a) {
    asm volatile("mbarrier.arrive.shared.b64 _, [%0];" :: "r"(a) : "memory");
}
__device__ __forceinline__ void mbar_wait(uint32_t a, uint32_t parity) {
    asm volatile(
        "{\n\t.reg .pred P;\n"
        "WL%=:\n\tmbarrier.try_wait.parity.shared.b64 P, [%0], %1;\n"
        "\t@P bra WD%=;\n\tbra WL%=;\nWD%=:\n\t}"
        :: "r"(a), "r"(parity) : "memory");
}
__device__ __forceinline__ void tma_load_3d(uint32_t dst, const CUtensorMap* tm,
                                            int cx, int cy, int cz, uint32_t mbar) {
    asm volatile(
        "cp.async.bulk.tensor.3d.shared::cta.global.tile.mbarrier::complete_tx::bytes "
        "[%0], [%1, {%2, %3, %4}], [%5];"
        :: "r"(dst), "l"(tm), "r"(cx), "r"(cy), "r"(cz), "r"(mbar) : "memory");
}

// ---------------- prologue: repack + RNA-round W ----------------
// One thread per (z=s*32+c, o) row: reads 32 floats of chunk c, writes the
// permuted 128B row. Source reads all hit one-or-two 128B lines (L1/L2 friendly).
__global__ void __launch_bounds__(256) repack_w_kernel(const float* __restrict__ w) {
    const int row = blockIdx.x * blockDim.x + threadIdx.x;   // 0 .. 262143
    const int o = row & 1023;
    const int z = row >> 10;          // s*32 + c
    const int s = z >> 5, c = z & 31;
    const float* src = w + (((size_t)s * OD + o) * HD) + c * BKF;
    float4 outv[8];
    const int xr = (o & 3) << 2;
    #pragma unroll
    for (int j = 0; j < 32; j++) {
        const int q = j >> 1;
        const int p = q ^ xr;
        const int k = (((p >> 2) & 3) << 3) | (p & 3) | ((j & 1) << 2);
        uint32_t r;
        asm("cvt.rna.tf32.f32 %0, %1;" : "=r"(r) : "f"(src[k]));
        reinterpret_cast<float*>(outv)[j] = __uint_as_float(r);
    }
    float4* dst = reinterpret_cast<float4*>(g_wp + (size_t)row * BKF);
    #pragma unroll
    for (int i = 0; i < 8; i++) dst[i] = outv[i];
}

// ---------------- main GEMM ----------------
__global__ __launch_bounds__(THREADS, 2)
void scl_tf32_v8(const __grid_constant__ CUtensorMap tma_x,
                 const __grid_constant__ CUtensorMap tma_w,
                 const int*   __restrict__ sid,
                 const float* __restrict__ bias,
                 float*       __restrict__ y) {
    extern __shared__ char smem[];
    const uint32_t sb = smem_u32(smem);

    const int b  = blockIdx.z;
    const int s  = __ldg(&sid[b]);
    const int m0 = blockIdx.y * BM;     // N (query) tile
    const int n0 = blockIdx.x * BN;     // O tile

    const int tid  = threadIdx.x;
    const int wid  = tid >> 5;
    const int lane = tid & 31;
    const int g    = lane >> 2;
    const int tg   = lane & 3;
    const int gx   = g << 2;            // SW128 XOR (A side, word units)
    const int bx   = (g & 3) << 2;      // baked XOR (B side, slot units)
    const int wm   = (wid & 1) * 64;
    const int wn   = (wid >> 1) * 64;

    if (tid == 0) {
        for (int st = 0; st < NST; st++) {
            mbar_init(sb + SMB_FULL(st), 1);
            mbar_init(sb + SMB_EMPTY(st), 4);
        }
    }
    __syncthreads();
    if (tid == 0) {
        for (int c = 0; c < NST; c++) {
            mbar_expect_tx(sb + SMB_FULL(c), STAGE_BYTES);
            tma_load_3d(sb + SM_A(c), &tma_x, c * BKF, m0, b, sb + SMB_FULL(c));
            tma_load_3d(sb + SM_B(c), &tma_w, 0, n0, s * CHUNKS + c, sb + SMB_FULL(c));
        }
    }

    float acc[4][8][4];
    #pragma unroll
    for (int i = 0; i < 4; i++)
        #pragma unroll
        for (int j = 0; j < 8; j++)
            #pragma unroll
            for (int k = 0; k < 4; k++) acc[i][j][k] = 0.f;

    uint32_t af0[4][4], bf0[8][2];
    uint32_t af1[4][4], bf1[8][2];

    // A: SW128-swizzled 128x32f tile, raw fp32 (HW truncates to tf32).
    // B: repacked layout — one LDS.64 per (col, col+4) pair, pre-rounded.
    auto ldfrag = [&](uint32_t af[4][4], uint32_t bf[8][2],
                      const float* A, const char* Bt, int kl) {
        const int c0k = (kl + tg) ^ gx;
        const int c1k = (kl + tg + 4) ^ gx;
        #pragma unroll
        for (int mi = 0; mi < 4; mi++) {
            const int r0 = wm + mi * 16 + g;
            af[mi][0] = __float_as_uint(A[ r0      * 32 + c0k]);
            af[mi][1] = __float_as_uint(A[(r0 + 8) * 32 + c0k]);
            af[mi][2] = __float_as_uint(A[ r0      * 32 + c1k]);
            af[mi][3] = __float_as_uint(A[(r0 + 8) * 32 + c1k]);
        }
        const int q = ((kl >> 1) | tg) ^ bx;     // slot index 0..15
        #pragma unroll
        for (int ni = 0; ni < 8; ni++) {
            const int row = wn + ni * 8 + g;
            const uint2 v = *reinterpret_cast<const uint2*>(Bt + row * 128 + q * 8);
            bf[ni][0] = v.x;
            bf[ni][1] = v.y;
        }
    };

    auto domma = [&](uint32_t af[4][4], uint32_t bf[8][2]) {
        #pragma unroll
        for (int mi = 0; mi < 4; mi++)
            #pragma unroll
            for (int ni = 0; ni < 8; ni++) {
                asm volatile(
                    "mma.sync.aligned.m16n8k8.row.col.f32.tf32.tf32.f32 "
                    "{%0,%1,%2,%3}, {%4,%5,%6,%7}, {%8,%9}, {%0,%1,%2,%3};\n"
                    : "+f"(acc[mi][ni][0]), "+f"(acc[mi][ni][1]),
                      "+f"(acc[mi][ni][2]), "+f"(acc[mi][ni][3])
                    : "r"(af[mi][0]), "r"(af[mi][1]),
                      "r"(af[mi][2]), "r"(af[mi][3]),
                      "r"(bf[ni][0]), "r"(bf[ni][1]));
            }
    };

    mbar_wait(sb + SMB_FULL(0), 0);
    ldfrag(af0, bf0, (const float*)(smem + SM_A(0)), smem + SM_B(0), 0);

    int wp = 0;
    for (int kt = 0; kt < CHUNKS; kt++) {
        const int st = kt % NST;
        const float* A  = (const float*)(smem + SM_A(st));
        const char*  Bt = smem + SM_B(st);

        ldfrag(af1, bf1, A, Bt, 8);
        domma(af0, bf0);
        ldfrag(af0, bf0, A, Bt, 16);
        domma(af1, bf1);

        // Early wait for next stage — drains behind the queued HMMA work
        const int ns = (kt + 1) % NST;
        if (kt + 1 < CHUNKS) {
            if (ns == 0) wp ^= 1;
            mbar_wait(sb + SMB_FULL(ns), (uint32_t)wp);
        }

        ldfrag(af1, bf1, A, Bt, 24);
        domma(af0, bf0);

        if (kt + 1 < CHUNKS)
            ldfrag(af0, bf0, (const float*)(smem + SM_A(ns)), smem + SM_B(ns), 0);
        domma(af1, bf1);

        if (lane == 0) mbar_arrive(sb + SMB_EMPTY(st));

        if (tid == 0 && kt + NST < CHUNKS) {
            mbar_wait(sb + SMB_EMPTY(st), (uint32_t)((kt / NST) & 1));
            mbar_expect_tx(sb + SMB_FULL(st), STAGE_BYTES);
            const int c = kt + NST;
            tma_load_3d(sb + SM_A(st), &tma_x, c * BKF, m0, b, sb + SMB_FULL(st));
            tma_load_3d(sb + SM_B(st), &tma_w, 0, n0, s * CHUNKS + c, sb + SMB_FULL(st));
        }
    }

    // Epilogue: bias add + store
    const float* bb = bias + (size_t)s * OD + n0;
    float* yb = y + (size_t)b * NQ * OD + (size_t)m0 * OD + n0;

    #pragma unroll
    for (int mi = 0; mi < 4; mi++) {
        const int row = wm + mi * 16 + g;
        #pragma unroll
        for (int ni = 0; ni < 8; ni++) {
            const int col = wn + ni * 8 + tg * 2;
            const float b0v = __ldg(&bb[col]);
            const float b1v = __ldg(&bb[col + 1]);
            float2 v0 = make_float2(acc[mi][ni][0] + b0v, acc[mi][ni][1] + b1v);
            float2 v1 = make_float2(acc[mi][ni][2] + b0v, acc[mi][ni][3] + b1v);
            *reinterpret_cast<float2*>(&yb[(size_t)row * OD + col])       = v0;
            *reinterpret_cast<float2*>(&yb[(size_t)(row + 8) * OD + col]) = v1;
        }
    }
}

// ---------------- host launch ----------------
typedef int (*PFN_encodeTiled)(
    CUtensorMap*, int, unsigned int, void*,
    const unsigned long long*, const unsigned long long*,
    const unsigned int*, const unsigned int*,
    int, int, int, int);

extern "C" void kernel_launch(void* const* d_in, const int* in_sizes, int n_in,
                              void* d_out, int out_size) {
    const float* x    = (const float*)d_in[0];
    const int*   sid  = (const int*)  d_in[1];
    const float* w    = (const float*)d_in[2];
    const float* bias = (const float*)d_in[3];
    float* y = (float*)d_out;

    // Prologue: repack + RNA-round W (262144 rows, 1 thread each)
    repack_w_kernel<<<1024, 256>>>(w);

    void* wscratch = nullptr;
    cudaGetSymbolAddress(&wscratch, g_wp);

    PFN_encodeTiled enc = nullptr;
    cudaDriverEntryPointQueryResult qr;
    cudaGetDriverEntryPoint("cuTensorMapEncodeTiled", (void**)&enc, cudaEnableDefault, &qr);

    // Enum ABI values: FLOAT32=7, interleave NONE=0, SWIZZLE_128B=3/NONE=0,
    // L2_128B=2, OOB NONE=0
    CUtensorMap tx{}, tw{};
    {
        unsigned long long dims[3]    = {HD, NQ, BATCH};
        unsigned long long strides[2] = {HD * 4ull, (unsigned long long)NQ * HD * 4ull};
        unsigned int box[3]           = {BKF, BM, 1};
        unsigned int es[3]            = {1, 1, 1};
        enc(&tx, 7, 3, (void*)x, dims, strides, box, es, 0, 3, 2, 0);
    }
    {
        // Repacked W: [z=256][o=1024][32 floats]; layout baked, no TMA swizzle
        unsigned long long dims[3]    = {BKF, OD, (unsigned long long)NSUBJ * CHUNKS};
        unsigned long long strides[2] = {BKF * 4ull, (unsigned long long)OD * BKF * 4ull};
        unsigned int box[3]           = {BKF, BN, 1};
        unsigned int es[3]            = {1, 1, 1};
        enc(&tw, 7, 3, wscratch, dims, strides, box, es, 0, 0, 2, 0);
    }

    cudaFuncSetAttribute(scl_tf32_v8, cudaFuncAttributeMaxDynamicSharedMemorySize, SMEM_TOTAL);

    dim3 grid(OD / BN, NQ / BM, BATCH);  // (8, 4, 32) = 1024 CTAs
    scl_tf32_v8<<<grid, THREADS, SMEM_TOTAL>>>(tx, tw, sid, bias, y);
}

// round 11
// speedup vs baseline: 1.1568x; 1.0045x over previous
#include <cuda_runtime.h>
#include <cuda.h>
#include <cstdint>

// Problem constants
#define BATCH 32
#define NQ    512
#define HD    1024
#define OD    1024
#define NSUBJ 8

// Tiling: CTA 128x128, 4 warps each computing 64x64; K chunk = 32 floats
#define BM 128
#define BN 128
#define BKF 32
#define CHUNKS (HD / BKF)    // 32
#define NST 3
#define THREADS 128

// SMEM layout
#define SMB_FULL(s)  ((s) * 8)
#define SMB_EMPTY(s) (24 + (s) * 8)
#define SM_A(s)      (1024 + (s) * 32768)
#define SM_B(s)      (SM_A(s) + 16384)
#define STAGE_BYTES  32768
#define SMEM_TOTAL   (1024 + NST * STAGE_BYTES)   // 99328

// Repacked W scratch: [s*32+c][o][32 floats], RNA-rounded to tf32, column-paired
// with per-row XOR baked in: slot q (0..15) holds logical cols (base, base+4),
// stored j = 2q+half;  q = ( (k&24)>>1 | (k&3) ) ^ ((o&3)<<2),  half = (k>>2)&1.
__device__ float g_wp[(size_t)NSUBJ * CHUNKS * OD * BKF];

__device__ __forceinline__ uint32_t smem_u32(const void* p) {
    return (uint32_t)__cvta_generic_to_shared(p);
}
__device__ __forceinline__ void mbar_init(uint32_t a, uint32_t cnt) {
    asm volatile("mbarrier.init.shared.b64 [%0], %1;" :: "r"(a), "r"(cnt) : "memory");
}
__device__ __forceinline__ void mbar_expect_tx(uint32_t a, uint32_t bytes) {
    asm volatile("mbarrier.arrive.expect_tx.shared.b64 _, [%0], %1;"
                 :: "r"(a), "r"(bytes) : "memory");
}
__device__ __forceinline__ void mbar_arrive(uint32_t a) {
    asm volatile("mbarrier.arrive.shared.b64 _, [%0];" :: "r"(a) : "memory");
}
__device__ __forceinline__ void mbar_wait(uint32_t a, uint32_t parity) {
    asm volatile(
        "{\n\t.reg .pred P;\n"
        "WL%=:\n\tmbarrier.try_wait.parity.shared.b64 P, [%0], %1;\n"
        "\t@P bra WD%=;\n\tbra WL%=;\nWD%=:\n\t}"
        :: "r"(a), "r"(parity) : "memory");
}
__device__ __forceinline__ void tma_load_3d(uint32_t dst, const CUtensorMap* tm,
                                            int cx, int cy, int cz, uint32_t mbar) {
    asm volatile(
        "cp.async.bulk.tensor.3d.shared::cta.global.tile.mbarrier::complete_tx::bytes "
        "[%0], [%1, {%2, %3, %4}], [%5];"
        :: "r"(dst), "l"(tm), "r"(cx), "r"(cy), "r"(cz), "r"(mbar) : "memory");
}

// ---------------- prologue: cooperative repack + RNA-round W ----------------
// 256 threads / 32 rows per block. Phase 1: coalesced float4 loads into smem
// (8 threads cover each 128B row). Phase 2: permuted gather from smem + RNA
// round, coalesced float4 stores. Same permutation as before, bit-identical.
#define RPB 32
__global__ void __launch_bounds__(256) repack_w_v2(const float* __restrict__ w) {
    __shared__ float sm[RPB][36];
    const int t    = threadIdx.x;
    const int rl   = t >> 3;                       // row within block 0..31
    const int part = t & 7;                        // 0..7 (16B quarter-segments)
    const int row  = blockIdx.x * RPB + rl;        // 0 .. 262143
    const int o = row & 1023;
    const int z = row >> 10;                       // s*32 + c
    const int s = z >> 5, c = z & 31;

    const float4 v = *reinterpret_cast<const float4*>(
        w + (((size_t)s * OD + o) * HD) + c * BKF + part * 4);
    sm[rl][part * 4 + 0] = v.x;
    sm[rl][part * 4 + 1] = v.y;
    sm[rl][part * 4 + 2] = v.z;
    sm[rl][part * 4 + 3] = v.w;
    __syncthreads();

    const int xr = (o & 3) << 2;
    float4 outv;
    float* po = reinterpret_cast<float*>(&outv);
    #pragma unroll
    for (int i = 0; i < 4; i++) {
        const int j = part * 4 + i;
        const int q = j >> 1;
        const int p = q ^ xr;
        const int k = (((p >> 2) & 3) << 3) | (p & 3) | ((j & 1) << 2);
        uint32_t r;
        asm("cvt.rna.tf32.f32 %0, %1;" : "=r"(r) : "f"(sm[rl][k]));
        po[i] = __uint_as_float(r);
    }
    *reinterpret_cast<float4*>(g_wp + (size_t)row * BKF + part * 4) = outv;
}

// ---------------- main GEMM (unchanged from R10 — 151us, tensor 75%) ----------
__global__ __launch_bounds__(THREADS, 2)
void scl_tf32_v8(const __grid_constant__ CUtensorMap tma_x,
                 const __grid_constant__ CUtensorMap tma_w,
                 const int*   __restrict__ sid,
                 const float* __restrict__ bias,
                 float*       __restrict__ y) {
    extern __shared__ char smem[];
    const uint32_t sb = smem_u32(smem);

    const int b  = blockIdx.z;
    const int s  = __ldg(&sid[b]);
    const int m0 = blockIdx.y * BM;     // N (query) tile
    const int n0 = blockIdx.x * BN;     // O tile

    const int tid  = threadIdx.x;
    const int wid  = tid >> 5;
    const int lane = tid & 31;
    const int g    = lane >> 2;
    const int tg   = lane & 3;
    const int gx   = g << 2;            // SW128 XOR (A side, word units)
    const int bx   = (g & 3) << 2;      // baked XOR (B side, slot units)
    const int wm   = (wid & 1) * 64;
    const int wn   = (wid >> 1) * 64;

    if (tid == 0) {
        for (int st = 0; st < NST; st++) {
            mbar_init(sb + SMB_FULL(st), 1);
            mbar_init(sb + SMB_EMPTY(st), 4);
        }
    }
    __syncthreads();
    if (tid == 0) {
        for (int c = 0; c < NST; c++) {
            mbar_expect_tx(sb + SMB_FULL(c), STAGE_BYTES);
            tma_load_3d(sb + SM_A(c), &tma_x, c * BKF, m0, b, sb + SMB_FULL(c));
            tma_load_3d(sb + SM_B(c), &tma_w, 0, n0, s * CHUNKS + c, sb + SMB_FULL(c));
        }
    }

    float acc[4][8][4];
    #pragma unroll
    for (int i = 0; i < 4; i++)
        #pragma unroll
        for (int j = 0; j < 8; j++)
            #pragma unroll
            for (int k = 0; k < 4; k++) acc[i][j][k] = 0.f;

    uint32_t af0[4][4], bf0[8][2];
    uint32_t af1[4][4], bf1[8][2];

    auto ldfrag = [&](uint32_t af[4][4], uint32_t bf[8][2],
                      const float* A, const char* Bt, int kl) {
        const int c0k = (kl + tg) ^ gx;
        const int c1k = (kl + tg + 4) ^ gx;
        #pragma unroll
        for (int mi = 0; mi < 4; mi++) {
            const int r0 = wm + mi * 16 + g;
            af[mi][0] = __float_as_uint(A[ r0      * 32 + c0k]);
            af[mi][1] = __float_as_uint(A[(r0 + 8) * 32 + c0k]);
            af[mi][2] = __float_as_uint(A[ r0      * 32 + c1k]);
            af[mi][3] = __float_as_uint(A[(r0 + 8) * 32 + c1k]);
        }
        const int q = ((kl >> 1) | tg) ^ bx;     // slot index 0..15
        #pragma unroll
        for (int ni = 0; ni < 8; ni++) {
            const int row = wn + ni * 8 + g;
            const uint2 v = *reinterpret_cast<const uint2*>(Bt + row * 128 + q * 8);
            bf[ni][0] = v.x;
            bf[ni][1] = v.y;
        }
    };

    auto domma = [&](uint32_t af[4][4], uint32_t bf[8][2]) {
        #pragma unroll
        for (int mi = 0; mi < 4; mi++)
            #pragma unroll
            for (int ni = 0; ni < 8; ni++) {
                asm volatile(
                    "mma.sync.aligned.m16n8k8.row.col.f32.tf32.tf32.f32 "
                    "{%0,%1,%2,%3}, {%4,%5,%6,%7}, {%8,%9}, {%0,%1,%2,%3};\n"
                    : "+f"(acc[mi][ni][0]), "+f"(acc[mi][ni][1]),
                      "+f"(acc[mi][ni][2]), "+f"(acc[mi][ni][3])
                    : "r"(af[mi][0]), "r"(af[mi][1]),
                      "r"(af[mi][2]), "r"(af[mi][3]),
                      "r"(bf[ni][0]), "r"(bf[ni][1]));
            }
    };

    mbar_wait(sb + SMB_FULL(0), 0);
    ldfrag(af0, bf0, (const float*)(smem + SM_A(0)), smem + SM_B(0), 0);

    int wp = 0;
    for (int kt = 0; kt < CHUNKS; kt++) {
        const int st = kt % NST;
        const float* A  = (const float*)(smem + SM_A(st));
        const char*  Bt = smem + SM_B(st);

        ldfrag(af1, bf1, A, Bt, 8);
        domma(af0, bf0);
        ldfrag(af0, bf0, A, Bt, 16);
        domma(af1, bf1);

        const int ns = (kt + 1) % NST;
        if (kt + 1 < CHUNKS) {
            if (ns == 0) wp ^= 1;
            mbar_wait(sb + SMB_FULL(ns), (uint32_t)wp);
        }

        ldfrag(af1, bf1, A, Bt, 24);
        domma(af0, bf0);

        if (kt + 1 < CHUNKS)
            ldfrag(af0, bf0, (const float*)(smem + SM_A(ns)), smem + SM_B(ns), 0);
        domma(af1, bf1);

        if (lane == 0) mbar_arrive(sb + SMB_EMPTY(st));

        if (tid == 0 && kt + NST < CHUNKS) {
            mbar_wait(sb + SMB_EMPTY(st), (uint32_t)((kt / NST) & 1));
            mbar_expect_tx(sb + SMB_FULL(st), STAGE_BYTES);
            const int c = kt + NST;
            tma_load_3d(sb + SM_A(st), &tma_x, c * BKF, m0, b, sb + SMB_FULL(st));
            tma_load_3d(sb + SM_B(st), &tma_w, 0, n0, s * CHUNKS + c, sb + SMB_FULL(st));
        }
    }

    // Epilogue: bias add + store
    const float* bb = bias + (size_t)s * OD + n0;
    float* yb = y + (size_t)b * NQ * OD + (size_t)m0 * OD + n0;

    #pragma unroll
    for (int mi = 0; mi < 4; mi++) {
        const int row = wm + mi * 16 + g;
        #pragma unroll
        for (int ni = 0; ni < 8; ni++) {
            const int col = wn + ni * 8 + tg * 2;
            const float b0v = __ldg(&bb[col]);
            const float b1v = __ldg(&bb[col + 1]);
            float2 v0 = make_float2(acc[mi][ni][0] + b0v, acc[mi][ni][1] + b1v);
            float2 v1 = make_float2(acc[mi][ni][2] + b0v, acc[mi][ni][3] + b1v);
            *reinterpret_cast<float2*>(&yb[(size_t)row * OD + col])       = v0;
            *reinterpret_cast<float2*>(&yb[(size_t)(row + 8) * OD + col]) = v1;
        }
    }
}

// ---------------- host launch ----------------
typedef int (*PFN_encodeTiled)(
    CUtensorMap*, int, unsigned int, void*,
    const unsigned long long*, const unsigned long long*,
    const unsigned int*, const unsigned int*,
    int, int, int, int);

extern "C" void kernel_launch(void* const* d_in, const int* in_sizes, int n_in,
                              void* d_out, int out_size) {
    const float* x    = (const float*)d_in[0];
    const int*   sid  = (const int*)  d_in[1];
    const float* w    = (const float*)d_in[2];
    const float* bias = (const float*)d_in[3];
    float* y = (float*)d_out;

    // Prologue: cooperative repack (262144 rows, 32 rows per 256-thread block)
    repack_w_v2<<<(NSUBJ * CHUNKS * OD) / RPB, 256>>>(w);

    void* wscratch = nullptr;
    cudaGetSymbolAddress(&wscratch, g_wp);

    PFN_encodeTiled enc = nullptr;
    cudaDriverEntryPointQueryResult qr;
    cudaGetDriverEntryPoint("cuTensorMapEncodeTiled", (void**)&enc, cudaEnableDefault, &qr);

    // Enum ABI values: FLOAT32=7, interleave NONE=0, SWIZZLE_128B=3/NONE=0,
    // L2_128B=2, OOB NONE=0
    CUtensorMap tx{}, tw{};
    {
        unsigned long long dims[3]    = {HD, NQ, BATCH};
        unsigned long long strides[2] = {HD * 4ull, (unsigned long long)NQ * HD * 4ull};
        unsigned int box[3]           = {BKF, BM, 1};
        unsigned int es[3]            = {1, 1, 1};
        enc(&tx, 7, 3, (void*)x, dims, strides, box, es, 0, 3, 2, 0);
    }
    {
        // Repacked W: [z=256][o=1024][32 floats]; layout baked, no TMA swizzle
        unsigned long long dims[3]    = {BKF, OD, (unsigned long long)NSUBJ * CHUNKS};
        unsigned long long strides[2] = {BKF * 4ull, (unsigned long long)OD * BKF * 4ull};
        unsigned int box[3]           = {BKF, BN, 1};
        unsigned int es[3]            = {1, 1, 1};
        enc(&tw, 7, 3, wscratch, dims, strides, box, es, 0, 0, 2, 0);
    }

    cudaFuncSetAttribute(scl_tf32_v8, cudaFuncAttributeMaxDynamicSharedMemorySize, SMEM_TOTAL);

    dim3 grid(OD / BN, NQ / BM, BATCH);  // (8, 4, 32) = 1024 CTAs
    scl_tf32_v8<<<grid, THREADS, SMEM_TOTAL>>>(tx, tw, sid, bias, y);
}